// round 13
// baseline (speedup 1.0000x reference)
#include <cuda_runtime.h>
#include <cstdint>

// ---------------------------------------------------------------------------
// NoteAxis: 2-layer LSTM, B=4096, U=128, 128 steps, teacher-forced.
// Persistent fp32 kernel, fma.rn.f32x2 packing a unit pair per register.
// R9: weights are NOT staged through SMEM. They live in a per-thread-
// contiguous permuted layout in global memory (L2-resident, 1MB) and are
// read with 2x LDG.128 per k per thread, plain C++ loads so ptxas schedules
// them. This removes cp.async and all 32 per-chunk barriers (5 barriers/step
// remain), letting LSU/LDG/FMA from different warps overlap instead of
// phase-alternating in lockstep.
// 128 CTAs x 256 threads; CTA owns 32 batch rows for all 128 steps.
// Thread tile: 2 units x 4 gates x 8 batch rows; cell state in registers.
// ---------------------------------------------------------------------------

#define B_TOTAL   4096
#define NSTEP     128
#define FDIM      127
#define UNITS     128
#define GATES     512
#define KDIM      256
#define BT        32
#define NCTA      (B_TOTAL / BT)       // 128
#define NTHREAD   256

// x region: rows 0..127 = x_t, 128..255 = h0, 256..383 = h1.
// Each row: 32 batch values DUPLICATED ((v,v) pairs) in 4 bank-swizzled
// slices of 8: slice s=b>>3 at byte offset s*64 + (s>>1)*16.
#define XROWF     68                   // floats per row (272 B, 16B-aligned)
#define XROWU     34                   // ull per row
#define NXROW     384

#define OFF_WO    (NXROW * XROWF)      // 26112
#define OFF_BO    (OFF_WO + UNITS)
#define SMEM_FLOATS (OFF_BO + 4)
#define SMEM_BYTES  (SMEM_FLOATS * 4)  // ~104.5 KB

// ---------------- persistent device scratch (no runtime alloc) -------------
// Permuted weights: ull (=float2 over unit pair) index = k*256 + wgrp*4 + g.
// Thread (wgrp) reads 32 contiguous bytes per k -> 2x LDG.128.
__device__ unsigned long long g_W0p[KDIM * GATES / 2];
__device__ unsigned long long g_W1p[KDIM * GATES / 2];
__device__ unsigned long long g_b0p[GATES / 2];   // index wgrp*4+g, (b,b+1)
__device__ unsigned long long g_b1p[GATES / 2];
__device__ float g_wout[UNITS];
__device__ float g_bout[1];

__device__ __forceinline__ unsigned long long pack2(float lo, float hi) {
    unsigned long long v;
    asm("mov.b64 %0, {%1, %2};" : "=l"(v) : "f"(lo), "f"(hi));
    return v;
}
__device__ __forceinline__ void unpack2(unsigned long long v, float& lo, float& hi) {
    asm("mov.b64 {%0, %1}, %2;" : "=f"(lo), "=f"(hi) : "l"(v));
}

// ---------------------------------------------------------------------------
__global__ void noteaxis_prep(const float* __restrict__ wih0, const float* __restrict__ whh0,
                              const float* __restrict__ bih0, const float* __restrict__ bhh0,
                              const float* __restrict__ wih1, const float* __restrict__ whh1,
                              const float* __restrict__ bih1, const float* __restrict__ bhh1,
                              const float* __restrict__ wout, const float* __restrict__ bout)
{
    int idx = blockIdx.x * blockDim.x + threadIdx.x;   // over 65536 ulls
    if (idx < KDIM * GATES / 2) {
        int k  = idx >> 8;        // 0..255
        int r  = idx & 255;       // wgrp*4 + g
        int wg = r >> 2;
        int g  = r & 3;
        int c0 = g * UNITS + 2 * wg;     // column (gate-major) of unit 2*wg
        int c1 = c0 + 1;
        float a0, a1, b0, b1;
        if (k < UNITS) {
            a0 = wih0[c0 * UNITS + k]; a1 = wih0[c1 * UNITS + k];
            b0 = wih1[c0 * UNITS + k]; b1 = wih1[c1 * UNITS + k];
        } else {
            a0 = whh0[c0 * UNITS + (k - UNITS)]; a1 = whh0[c1 * UNITS + (k - UNITS)];
            b0 = whh1[c0 * UNITS + (k - UNITS)]; b1 = whh1[c1 * UNITS + (k - UNITS)];
        }
        g_W0p[idx] = pack2(a0, a1);
        g_W1p[idx] = pack2(b0, b1);
    }
    if (idx < GATES / 2) {
        int wg = idx >> 2;
        int g  = idx & 3;
        int c0 = g * UNITS + 2 * wg;
        g_b0p[idx] = pack2(bih0[c0] + bhh0[c0], bih0[c0 + 1] + bhh0[c0 + 1]);
        g_b1p[idx] = pack2(bih1[c0] + bhh1[c0], bih1[c0 + 1] + bhh1[c0 + 1]);
    }
    if (idx < UNITS) g_wout[idx] = wout[idx];
    if (idx == 0)    g_bout[0]   = bout[0];
}

// ---------------------------------------------------------------------------
__device__ __forceinline__ float ftanh_(float x) {
    float r;
    asm("tanh.approx.f32 %0, %1;" : "=f"(r) : "f"(x));
    return r;
}
__device__ __forceinline__ float fsig(float x) {
    return fmaf(0.5f, ftanh_(0.5f * x), 0.5f);
}

// byte offset of (dup'd) batch element b within an x row
__device__ __forceinline__ uint32_t bslice(int b) {
    int s = b >> 3;
    return (uint32_t)(s * 64 + (s >> 1) * 16 + (b & 7) * 8);
}

// GEMM over K=256: acc[r][g] += x[k][pair r] * w[k][unit pair, gate g].
// x from SMEM (plain loads -> LDS.128 pairs), w straight from L2 (LDG.128).
// No barriers inside; ptxas schedules/hoists freely.
__device__ __forceinline__ void gemm256(const unsigned long long* __restrict__ sxu,
                                        int xbase,                       // ull index of k=0 row + slice
                                        const ulonglong2* __restrict__ w, // + wgrp*2 already
                                        unsigned long long (&acc)[8][4])
{
#pragma unroll 4
    for (int k = 0; k < KDIM; ++k) {
        ulonglong2 wA = w[0];          // gates i, f   (f32x2 over unit pair)
        ulonglong2 wB = w[1];          // gates g, o
        w += 128;                      // next k (128 ull2 per k)
        const unsigned long long* xr = sxu + xbase;
        xbase += XROWU;
#pragma unroll
        for (int r = 0; r < 8; ++r) {
            unsigned long long xv = xr[r];
            asm("fma.rn.f32x2 %0, %1, %2, %0;" : "+l"(acc[r][0]) : "l"(xv), "l"(wA.x));
            asm("fma.rn.f32x2 %0, %1, %2, %0;" : "+l"(acc[r][1]) : "l"(xv), "l"(wA.y));
            asm("fma.rn.f32x2 %0, %1, %2, %0;" : "+l"(acc[r][2]) : "l"(xv), "l"(wB.x));
            asm("fma.rn.f32x2 %0, %1, %2, %0;" : "+l"(acc[r][3]) : "l"(xv), "l"(wB.y));
        }
    }
}

// Gates -> nonlinearity -> cell update -> dup'd h stores (plain stores).
__device__ __forceinline__ void lstm_pointwise(unsigned long long (&acc)[8][4],
                                               float (&cs)[8][2],
                                               float* hrow0, float* hrow1)
{
#pragma unroll
    for (int r = 0; r < 8; ++r) {
        float i0, i1, f0, f1, g0, g1, o0, o1;
        unpack2(acc[r][0], i0, i1);
        unpack2(acc[r][1], f0, f1);
        unpack2(acc[r][2], g0, g1);
        unpack2(acc[r][3], o0, o1);
        float c0 = fsig(f0) * cs[r][0] + fsig(i0) * ftanh_(g0);
        float c1 = fsig(f1) * cs[r][1] + fsig(i1) * ftanh_(g1);
        cs[r][0] = c0;
        cs[r][1] = c1;
        float h0 = fsig(o0) * ftanh_(c0);
        float h1 = fsig(o1) * ftanh_(c1);
        reinterpret_cast<float2*>(hrow0)[r] = make_float2(h0, h0);
        reinterpret_cast<float2*>(hrow1)[r] = make_float2(h1, h1);
    }
}

// ---------------------------------------------------------------------------
__global__ void __launch_bounds__(NTHREAD, 1)
noteaxis_lstm(const float* __restrict__ nf, const float* __restrict__ tg,
              float* __restrict__ out)
{
    extern __shared__ float smem[];
    const int tid  = threadIdx.x;
    const int wgrp = tid >> 2;   // 0..63 : unit pair {2*wgrp, 2*wgrp+1}
    const int bgrp = tid & 3;    // 0..3  : batch rows 8*bgrp..8*bgrp+7
    const int b0   = blockIdx.x * BT;

    const unsigned long long* sxu = reinterpret_cast<const unsigned long long*>(smem);

    // Zero x/h region; stage wout/bout.
    for (int i = tid; i < OFF_WO; i += NTHREAD) smem[i] = 0.0f;
    if (tid < UNITS) smem[OFF_WO + tid] = g_wout[tid];
    if (tid == 0)    smem[OFF_BO] = g_bout[0];

    float cs0[8][2], cs1[8][2];
#pragma unroll
    for (int r = 0; r < 8; ++r) {
        cs0[r][0] = 0.0f; cs0[r][1] = 0.0f;
        cs1[r][0] = 0.0f; cs1[r][1] = 0.0f;
    }

    const int xoffU = (int)(bslice(8 * bgrp) >> 3);          // ull offset in row
    const int xoffF = (int)(bslice(8 * bgrp) >> 2);          // float offset
    float* h0row0 = smem + (128 + 2 * wgrp) * XROWF + xoffF; // unit 2w
    float* h0row1 = h0row0 + XROWF;                          // unit 2w+1
    float* h1row0 = smem + (256 + 2 * wgrp) * XROWF + xoffF;
    float* h1row1 = h1row0 + XROWF;

    const ulonglong2* w0 = reinterpret_cast<const ulonglong2*>(g_W0p) + wgrp * 2;
    const ulonglong2* w1 = reinterpret_cast<const ulonglong2*>(g_W1p) + wgrp * 2;
    const ulonglong2* b0p = reinterpret_cast<const ulonglong2*>(g_b0p) + wgrp * 2;
    const ulonglong2* b1p = reinterpret_cast<const ulonglong2*>(g_b1p) + wgrp * 2;

    __syncthreads();

    for (int t = 0; t < NSTEP; ++t) {
        // ---- stage x_t (dup'd) into rows 0..127 ---------------------------
#pragma unroll
        for (int i = 0; i < 16; ++i) {
            int idx = tid + i * NTHREAD;     // 0..4095
            int b = idx >> 7;
            int f = idx & 127;
            float v;
            if (f < FDIM)
                v = nf[((b0 + b) * NSTEP + t) * FDIM + f];
            else
                v = (t > 0) ? tg[(b0 + b) * NSTEP + (t - 1)] : 0.0f;
            *reinterpret_cast<float2*>(smem + f * XROWF + (bslice(b) >> 2)) =
                make_float2(v, v);
        }
        __syncthreads();   // A: x staged

        unsigned long long acc[8][4];

        // ================= layer 0 : gates = [x|h0] @ W0 + b0 ==============
        {
            ulonglong2 bA = b0p[0], bB = b0p[1];
#pragma unroll
            for (int r = 0; r < 8; ++r) {
                acc[r][0] = bA.x; acc[r][1] = bA.y;
                acc[r][2] = bB.x; acc[r][3] = bB.y;
            }
        }
        gemm256(sxu, xoffU, w0, acc);                 // reads rows 0..255
        __syncthreads();   // B: everyone done reading h0(prev)
        lstm_pointwise(acc, cs0, h0row0, h0row1);     // writes rows 128..255
        __syncthreads();   // C: h0 visible

        // ================= layer 1 : gates = [h0|h1] @ W1 + b1 =============
        {
            ulonglong2 bA = b1p[0], bB = b1p[1];
#pragma unroll
            for (int r = 0; r < 8; ++r) {
                acc[r][0] = bA.x; acc[r][1] = bA.y;
                acc[r][2] = bB.x; acc[r][3] = bB.y;
            }
        }
        gemm256(sxu, 128 * XROWU + xoffU, w1, acc);   // reads rows 128..383
        __syncthreads();   // D: everyone done reading h1(prev)
        lstm_pointwise(acc, cs1, h1row0, h1row1);     // writes rows 256..383
        __syncthreads();   // E: h1 visible

        // ---------------- output: sigmoid(h1 . wout + bout) ---------------
        {
            int rowb = tid >> 3;
            int l8   = tid & 7;
            int so   = (int)(bslice(rowb) >> 2);
            float s = 0.0f;
#pragma unroll
            for (int jj = 0; jj < 16; ++jj) {
                int u = l8 + 8 * jj;
                s += smem[(256 + u) * XROWF + so] * smem[OFF_WO + u];
            }
            s += __shfl_xor_sync(0xffffffffu, s, 1);
            s += __shfl_xor_sync(0xffffffffu, s, 2);
            s += __shfl_xor_sync(0xffffffffu, s, 4);
            if (l8 == 0)
                out[(b0 + rowb) * NSTEP + t] = fsig(s + smem[OFF_BO]);
        }
        // Next-step x staging writes rows 0..127 only; epilogue reads rows
        // 256..383 — disjoint, and barrier A orders staging before the gemm.
    }
}

// ---------------------------------------------------------------------------
extern "C" void kernel_launch(void* const* d_in, const int* in_sizes, int n_in,
                              void* d_out, int out_size)
{
    const float* nf   = (const float*)d_in[0];
    const float* tg   = (const float*)d_in[1];
    const float* wih0 = (const float*)d_in[2];
    const float* whh0 = (const float*)d_in[3];
    const float* bih0 = (const float*)d_in[4];
    const float* bhh0 = (const float*)d_in[5];
    const float* wih1 = (const float*)d_in[6];
    const float* whh1 = (const float*)d_in[7];
    const float* bih1 = (const float*)d_in[8];
    const float* bhh1 = (const float*)d_in[9];
    const float* wout = (const float*)d_in[10];
    const float* bout = (const float*)d_in[11];
    float* out = (float*)d_out;

    cudaFuncSetAttribute(noteaxis_lstm, cudaFuncAttributeMaxDynamicSharedMemorySize, SMEM_BYTES);

    noteaxis_prep<<<(KDIM * GATES / 2 + 255) / 256, 256>>>(wih0, whh0, bih0, bhh0,
                                                           wih1, whh1, bih1, bhh1,
                                                           wout, bout);
    noteaxis_lstm<<<NCTA, NTHREAD, SMEM_BYTES>>>(nf, tg, out);
}

// round 15
// speedup vs baseline: 2.0923x; 2.0923x over previous
#include <cuda_runtime.h>
#include <cuda_bf16.h>
#include <cstdint>

// ---------------------------------------------------------------------------
// NoteAxis 2-layer LSTM (B=4096, U=128, 128 steps) — warp-level mma.sync bf16
// (baseline PTX; the harness targets sm_103 without 'a', so tcgen05 is
// unavailable). 3-term hi/lo bf16 split gives fp32-grade GEMM accuracy.
// 128 CTAs x 256 threads (8 warps); CTA owns 32 batch rows for all steps.
// Warp (mh,nq) owns C[16 rows,128 cols]; columns are unit-major (n=4u+g) so
// one shfl.xor(1) exchange gives each thread all 4 gates of one unit:
// cell state lives in registers (16 cells/thread/layer) across all steps.
// Weights pre-packed into mma-fragment-major images, streamed L2->SMEM with
// the proven cp.async triple-buffer ring; W_hi pieces feed 2 mma passes
// (A_hi and A_lo), W_lo pieces feed 1 (A_hi).
// ---------------------------------------------------------------------------

#define NSTEP 128
#define FDIM  127
#define BT    32
#define NCTA  128
#define NT    256

#define ABLK  8704      // one A block: 32 rows x 272 bytes (128 bf16 + pad)
#define ASTR  272
#define PIECE 16384     // one weight piece: kchunk x 64 ntiles x 256B
#define NSEQ  64        // pieces per step: 2 layers x (16 Whi + 16 Wlo)

// smem byte offsets
#define SM_A     0              // 6 blocks: Xhi Xlo H0hi H0lo H1hi H1lo
#define SM_RING  52224          // 3 x 16KB
#define SM_BIAS  101376         // 2 x 512 floats (unit-major n)
#define SM_WOUT  105472         // 128 floats
#define SM_BOUT  105984
#define SM_PART  106000         // 4 x 32 floats
#define SMEM_SZ  106512

// ---------------- persistent device scratch --------------------------------
// fragment-major weights: u64 index = ((piece)*2048) + gnt*32 + lane
// piece s: L=s>>5, T=(s>>4)&1 (0=hi,1=lo), kc=s&15
__device__ unsigned long long g_Bf[NSEQ * 2048];
__device__ float g_biasn[1024];     // [L][n], n = 4u+g
__device__ float g_wout[128], g_bout[1];

// ---------------------------------------------------------------------------
__global__ void noteaxis_prep(const float* __restrict__ wih0, const float* __restrict__ whh0,
                              const float* __restrict__ bih0, const float* __restrict__ bhh0,
                              const float* __restrict__ wih1, const float* __restrict__ whh1,
                              const float* __restrict__ bih1, const float* __restrict__ bhh1,
                              const float* __restrict__ wout, const float* __restrict__ bout)
{
    int idx = blockIdx.x * blockDim.x + threadIdx.x;
    if (idx < NSEQ * 2048) {
        int s = idx >> 11, r = idx & 2047;
        int gnt = r >> 5, lane = r & 31;
        int L = s >> 5, T = (s >> 4) & 1, kc = s & 15;
        int n = gnt * 8 + (lane >> 2);
        int u = n >> 2, g = n & 3, col = g * 128 + u;   // PyTorch gate-major col
        const float* wih = L ? wih1 : wih0;
        const float* whh = L ? whh1 : whh0;
        unsigned long long v = 0;
#pragma unroll
        for (int rg = 0; rg < 2; ++rg) {
            unsigned int pk = 0;
#pragma unroll
            for (int half = 0; half < 2; ++half) {
                int k = kc * 16 + (lane & 3) * 2 + rg * 8 + half;
                float w = (k < 128) ? wih[col * 128 + k] : whh[col * 128 + (k - 128)];
                __nv_bfloat16 hi = __float2bfloat16_rn(w);
                __nv_bfloat16 e = T ? __float2bfloat16_rn(w - __bfloat162float(hi)) : hi;
                pk |= (unsigned int)__bfloat16_as_ushort(e) << (16 * half);
            }
            v |= (unsigned long long)pk << (32 * rg);
        }
        g_Bf[idx] = v;
    }
    if (idx < 1024) {
        int L = idx >> 9, n = idx & 511;
        int u = n >> 2, g = n & 3, col = g * 128 + u;
        g_biasn[idx] = L ? (bih1[col] + bhh1[col]) : (bih0[col] + bhh0[col]);
    }
    if (idx < 128) g_wout[idx] = wout[idx];
    if (idx == 0)  g_bout[0] = bout[0];
}

// ---------------------------------------------------------------------------
__device__ __forceinline__ float ftanh_(float x) {
    float r; asm("tanh.approx.f32 %0, %1;" : "=f"(r) : "f"(x)); return r;
}
__device__ __forceinline__ float fsig(float x) { return fmaf(0.5f, ftanh_(0.5f * x), 0.5f); }

__device__ __forceinline__ void prefetch_piece(uint32_t dst, const char* src, int tid) {
    uint32_t d = dst + tid * 16;
    src += tid * 16;
#pragma unroll
    for (int i = 0; i < 4; ++i) {
        asm volatile("cp.async.cg.shared.global [%0], [%1], 16;" :: "r"(d), "l"(src) : "memory");
        d += NT * 16; src += NT * 16;
    }
    asm volatile("cp.async.commit_group;" ::: "memory");
}

__device__ __forceinline__ void ldA(uint32_t ad, uint32_t (&a)[4]) {
    asm volatile("ld.shared.b32 %0, [%1];" : "=r"(a[0]) : "r"(ad));
    asm volatile("ld.shared.b32 %0, [%1];" : "=r"(a[1]) : "r"(ad + 8 * ASTR));
    asm volatile("ld.shared.b32 %0, [%1];" : "=r"(a[2]) : "r"(ad + 16));
    asm volatile("ld.shared.b32 %0, [%1];" : "=r"(a[3]) : "r"(ad + 8 * ASTR + 16));
}

__device__ __forceinline__ void mma16816(float* c, const uint32_t (&a)[4],
                                         uint32_t b0, uint32_t b1) {
    asm volatile("mma.sync.aligned.m16n8k16.row.col.f32.bf16.bf16.f32 "
                 "{%0,%1,%2,%3}, {%4,%5,%6,%7}, {%8,%9}, {%0,%1,%2,%3};"
                 : "+f"(c[0]), "+f"(c[1]), "+f"(c[2]), "+f"(c[3])
                 : "r"(a[0]), "r"(a[1]), "r"(a[2]), "r"(a[3]), "r"(b0), "r"(b1));
}

// ---------------------------------------------------------------------------
__global__ void __launch_bounds__(NT, 1)
noteaxis_lstm(const float* __restrict__ nf, const float* __restrict__ tg,
              float* __restrict__ out)
{
    extern __shared__ __align__(16) char smem[];
    const uint32_t sb = (uint32_t)__cvta_generic_to_shared(smem);
    const int tid = threadIdx.x, warp = tid >> 5, lane = tid & 31;
    const int mh = warp & 1, nq = warp >> 1;       // warp tile: rows mh*16.., cols nq*128..
    const int b0 = blockIdx.x * BT;
    const int lr = lane >> 2, lc = lane & 3;

    // zero A blocks (h starts at 0); stage bias/wout/bout
    for (int i = tid; i < 6 * ABLK / 4; i += NT)
        reinterpret_cast<uint32_t*>(smem)[i] = 0u;
    for (int i = tid; i < 1024; i += NT)
        reinterpret_cast<float*>(smem + SM_BIAS)[i] = g_biasn[i];
    if (tid < 128) reinterpret_cast<float*>(smem + SM_WOUT)[tid] = g_wout[tid];
    if (tid == 0)  reinterpret_cast<float*>(smem + SM_BOUT)[0] = g_bout[0];

    // per-thread epilogue constants
    const int rowg = mh * 16 + lr + 8 * (lane & 1);        // this thread's C row
    float cs0[16], cs1[16];
#pragma unroll
    for (int i = 0; i < 16; ++i) { cs0[i] = 0.f; cs1[i] = 0.f; }

    // A-fragment per-thread base (block offset added per piece)
    const uint32_t aoff = (uint32_t)((mh * 16 + lr) * ASTR + lc * 4);
    // B fragment base within a ring buffer
    const uint32_t boff = (uint32_t)(nq * 16 * 256 + lane * 8);

    // prologue: prefetch pieces 0,1
    prefetch_piece(sb + SM_RING, reinterpret_cast<const char*>(g_Bf), tid);
    prefetch_piece(sb + SM_RING + PIECE, reinterpret_cast<const char*>(g_Bf) + PIECE, tid);
    int pseq = 2, gbuf = 0;
    __syncthreads();

    float* part = reinterpret_cast<float*>(smem + SM_PART);

    for (int t = 0; t < NSTEP; ++t) {
        // ---- stage x_t split hi/lo into blocks 0,1 -------------------------
#pragma unroll
        for (int i = 0; i < 16; ++i) {
            int idx = tid + i * NT;          // 0..4095
            int row = idx >> 7, f = idx & 127;
            float v;
            if (f < FDIM) v = nf[((size_t)(b0 + row) * NSTEP + t) * FDIM + f];
            else          v = t ? tg[(size_t)(b0 + row) * NSTEP + t - 1] : 0.f;
            __nv_bfloat16 hi = __float2bfloat16_rn(v);
            __nv_bfloat16 lo = __float2bfloat16_rn(v - __bfloat162float(hi));
            int eo = row * (ASTR / 2) + f;
            reinterpret_cast<__nv_bfloat16*>(smem)[eo] = hi;
            reinterpret_cast<__nv_bfloat16*>(smem + ABLK)[eo] = lo;
        }
        // barrier comes from the first piece's wait+sync below

#pragma unroll 1
        for (int L = 0; L < 2; ++L) {
            float acc[64];
#pragma unroll
            for (int i = 0; i < 64; ++i) acc[i] = 0.f;

#pragma unroll 1
            for (int p = 0; p < 32; ++p) {
                asm volatile("cp.async.wait_group 1;" ::: "memory");
                __syncthreads();
                int tbuf = gbuf + 2; if (tbuf >= 3) tbuf -= 3;
                prefetch_piece(sb + SM_RING + (uint32_t)tbuf * PIECE,
                               reinterpret_cast<const char*>(g_Bf) + (size_t)pseq * PIECE, tid);
                if (++pseq == NSEQ) pseq = 0;

                const int T = p >> 4, kc = p & 15;
                const int hiblk = (L == 0) ? (kc < 8 ? 0 : 2) : (kc < 8 ? 2 : 4);
                const uint32_t kb = (uint32_t)((kc & 7) * 32);   // klocal bytes
                uint32_t aH[4], aL[4];
                ldA(sb + (uint32_t)hiblk * ABLK + aoff + kb, aH);
                if (T == 0) ldA(sb + (uint32_t)(hiblk + 1) * ABLK + aoff + kb, aL);

                uint32_t bb = sb + SM_RING + (uint32_t)gbuf * PIECE + boff;
#pragma unroll
                for (int nt = 0; nt < 16; ++nt) {
                    uint32_t w0, w1;
                    asm volatile("ld.shared.v2.u32 {%0, %1}, [%2];"
                                 : "=r"(w0), "=r"(w1) : "r"(bb + (uint32_t)nt * 256));
                    mma16816(acc + nt * 4, aH, w0, w1);
                    if (T == 0) mma16816(acc + nt * 4, aL, w0, w1);
                }
                if (++gbuf == 3) gbuf = 0;
            }
            __syncthreads();   // all GEMM reads done before epilogue h writes

            // ---------------- epilogue: gates -> cells -> h ----------------
            const float* bias = reinterpret_cast<const float*>(smem + SM_BIAS) + L * 512;
            const float* wo = reinterpret_cast<const float*>(smem + SM_WOUT);
            float* cs = L ? cs1 : cs0;
            __nv_bfloat16* Hhi = reinterpret_cast<__nv_bfloat16*>(smem + (size_t)(2 + 2 * L) * ABLK);
            __nv_bfloat16* Hlo = reinterpret_cast<__nv_bfloat16*>(smem + (size_t)(3 + 2 * L) * ABLK);
            float dot = 0.f;
#pragma unroll
            for (int nt = 0; nt < 16; ++nt) {
                float c0 = acc[nt * 4], c1 = acc[nt * 4 + 1];
                float c2 = acc[nt * 4 + 2], c3 = acc[nt * 4 + 3];
                int n0 = nq * 128 + nt * 8 + 2 * lc;
                float2 bb2 = *reinterpret_cast<const float2*>(bias + n0);
                c0 += bb2.x; c1 += bb2.y; c2 += bb2.x; c3 += bb2.y;
                bool odd = (lane & 1);
                float v1 = __shfl_xor_sync(0xffffffffu, odd ? c0 : c2, 1);
                float v2 = __shfl_xor_sync(0xffffffffu, odd ? c1 : c3, 1);
                float gi = odd ? v1 : c0;
                float gf = odd ? v2 : c1;
                float gg = odd ? c2 : v1;
                float go = odd ? c3 : v2;
                float c = fsig(gf) * cs[nt] + fsig(gi) * ftanh_(gg);
                cs[nt] = c;
                float h = fsig(go) * ftanh_(c);
                int u = nq * 32 + nt * 2 + (lc >> 1);
                __nv_bfloat16 hh = __float2bfloat16_rn(h);
                __nv_bfloat16 hl = __float2bfloat16_rn(h - __bfloat162float(hh));
                int eo = rowg * (ASTR / 2) + u;
                Hhi[eo] = hh;
                Hlo[eo] = hl;
                if (L) dot = fmaf(h, wo[u], dot);
            }
            if (L) {
                dot += __shfl_xor_sync(0xffffffffu, dot, 2);
                if ((lane & 2) == 0) part[nq * 32 + rowg] = dot;
            }
            // next loop's first piece-barrier orders h-writes before reads
        }

        __syncthreads();   // h1 + partials visible
        if (tid < 32) {
            float s = part[tid] + part[32 + tid] + part[64 + tid] + part[96 + tid]
                    + reinterpret_cast<const float*>(smem + SM_BOUT)[0];
            out[(size_t)(b0 + tid) * NSTEP + t] = fsig(s);
        }
        // next-step x staging writes blocks 0,1 only (out reads PART; H blocks
        // untouched); the first piece-barrier of the next step orders staging.
    }
}

// ---------------------------------------------------------------------------
extern "C" void kernel_launch(void* const* d_in, const int* in_sizes, int n_in,
                              void* d_out, int out_size)
{
    const float* nf   = (const float*)d_in[0];
    const float* tg   = (const float*)d_in[1];
    const float* wih0 = (const float*)d_in[2];
    const float* whh0 = (const float*)d_in[3];
    const float* bih0 = (const float*)d_in[4];
    const float* bhh0 = (const float*)d_in[5];
    const float* wih1 = (const float*)d_in[6];
    const float* whh1 = (const float*)d_in[7];
    const float* bih1 = (const float*)d_in[8];
    const float* bhh1 = (const float*)d_in[9];
    const float* wout = (const float*)d_in[10];
    const float* bout = (const float*)d_in[11];
    float* out = (float*)d_out;

    cudaFuncSetAttribute(noteaxis_lstm, cudaFuncAttributeMaxDynamicSharedMemorySize, SMEM_SZ);

    noteaxis_prep<<<(NSEQ * 2048 + 255) / 256, 256>>>(wih0, whh0, bih0, bhh0,
                                                      wih1, whh1, bih1, bhh1,
                                                      wout, bout);
    noteaxis_lstm<<<NCTA, NT, SMEM_SZ>>>(nf, tg, out);
}

// round 16
// speedup vs baseline: 2.2122x; 1.0573x over previous
#include <cuda_runtime.h>
#include <cuda_bf16.h>
#include <cstdint>

// ---------------------------------------------------------------------------
// NoteAxis 2-layer LSTM (B=4096, U=128, 128 steps) — warp-level mma.sync bf16,
// 3-term hi/lo split (fp32-grade accuracy, measured 3.7e-7 in R14).
// R15: 512 threads / 16 warps (warp tile 16x64) for cross-warp overlap of
// LDS and HMMA phases; weight pieces paired into 32KB groups to halve the
// per-step barrier count (32 instead of 64). Math identical to R14.
// ---------------------------------------------------------------------------

#define NSTEP 128
#define FDIM  127
#define BT    32
#define NCTA  128
#define NT    512

#define ABLK  8704      // one A block: 32 rows x 272 bytes (128 bf16 + pad)
#define ASTR  272
#define PIECE 16384     // one weight piece: 1 kchunk x 64 ntiles x 256B
#define GROUP 32768     // two consecutive pieces
#define NGRP  32        // groups per step (2 layers x 16)

// smem byte offsets
#define SM_A     0              // 6 blocks: Xhi Xlo H0hi H0lo H1hi H1lo
#define SM_RING  52224          // 3 x 32KB
#define SM_BIAS  150528         // 2 x 512 floats (unit-major n)
#define SM_WOUT  154624         // 128 floats
#define SM_BOUT  155136
#define SM_PART  155152         // 8 x 32 floats
#define SMEM_SZ  156176

// ---------------- persistent device scratch --------------------------------
// fragment-major weights: u64 index = piece*2048 + gnt*32 + lane
// piece s: L=s>>5, T=(s>>4)&1 (0=hi,1=lo), kc=s&15
__device__ unsigned long long g_Bf[64 * 2048];
__device__ float g_biasn[1024];     // [L][n], n = 4u+g
__device__ float g_wout[128], g_bout[1];

// ---------------------------------------------------------------------------
__global__ void noteaxis_prep(const float* __restrict__ wih0, const float* __restrict__ whh0,
                              const float* __restrict__ bih0, const float* __restrict__ bhh0,
                              const float* __restrict__ wih1, const float* __restrict__ whh1,
                              const float* __restrict__ bih1, const float* __restrict__ bhh1,
                              const float* __restrict__ wout, const float* __restrict__ bout)
{
    int idx = blockIdx.x * blockDim.x + threadIdx.x;
    if (idx < 64 * 2048) {
        int s = idx >> 11, r = idx & 2047;
        int gnt = r >> 5, lane = r & 31;
        int L = s >> 5, T = (s >> 4) & 1, kc = s & 15;
        int n = gnt * 8 + (lane >> 2);
        int u = n >> 2, g = n & 3, col = g * 128 + u;   // PyTorch gate-major col
        const float* wih = L ? wih1 : wih0;
        const float* whh = L ? whh1 : whh0;
        unsigned long long v = 0;
#pragma unroll
        for (int rg = 0; rg < 2; ++rg) {
            unsigned int pk = 0;
#pragma unroll
            for (int half = 0; half < 2; ++half) {
                int k = kc * 16 + (lane & 3) * 2 + rg * 8 + half;
                float w = (k < 128) ? wih[col * 128 + k] : whh[col * 128 + (k - 128)];
                __nv_bfloat16 hi = __float2bfloat16_rn(w);
                __nv_bfloat16 e = T ? __float2bfloat16_rn(w - __bfloat162float(hi)) : hi;
                pk |= (unsigned int)__bfloat16_as_ushort(e) << (16 * half);
            }
            v |= (unsigned long long)pk << (32 * rg);
        }
        g_Bf[idx] = v;
    }
    if (idx < 1024) {
        int L = idx >> 9, n = idx & 511;
        int u = n >> 2, g = n & 3, col = g * 128 + u;
        g_biasn[idx] = L ? (bih1[col] + bhh1[col]) : (bih0[col] + bhh0[col]);
    }
    if (idx < 128) g_wout[idx] = wout[idx];
    if (idx == 0)  g_bout[0] = bout[0];
}

// ---------------------------------------------------------------------------
__device__ __forceinline__ float ftanh_(float x) {
    float r; asm("tanh.approx.f32 %0, %1;" : "=f"(r) : "f"(x)); return r;
}
__device__ __forceinline__ float fsig(float x) { return fmaf(0.5f, ftanh_(0.5f * x), 0.5f); }

__device__ __forceinline__ void prefetch_group(uint32_t dst, const char* src, int tid) {
    uint32_t d = dst + tid * 16;
    src += tid * 16;
#pragma unroll
    for (int i = 0; i < 4; ++i) {   // 512 thr x 4 x 16B = 32KB
        asm volatile("cp.async.cg.shared.global [%0], [%1], 16;" :: "r"(d), "l"(src) : "memory");
        d += NT * 16; src += NT * 16;
    }
    asm volatile("cp.async.commit_group;" ::: "memory");
}

__device__ __forceinline__ void ldA(uint32_t ad, uint32_t (&a)[4]) {
    asm volatile("ld.shared.b32 %0, [%1];" : "=r"(a[0]) : "r"(ad));
    asm volatile("ld.shared.b32 %0, [%1];" : "=r"(a[1]) : "r"(ad + 8 * ASTR));
    asm volatile("ld.shared.b32 %0, [%1];" : "=r"(a[2]) : "r"(ad + 16));
    asm volatile("ld.shared.b32 %0, [%1];" : "=r"(a[3]) : "r"(ad + 8 * ASTR + 16));
}

__device__ __forceinline__ void mma16816(float* c, const uint32_t (&a)[4],
                                         uint32_t b0, uint32_t b1) {
    asm volatile("mma.sync.aligned.m16n8k16.row.col.f32.bf16.bf16.f32 "
                 "{%0,%1,%2,%3}, {%4,%5,%6,%7}, {%8,%9}, {%0,%1,%2,%3};"
                 : "+f"(c[0]), "+f"(c[1]), "+f"(c[2]), "+f"(c[3])
                 : "r"(a[0]), "r"(a[1]), "r"(a[2]), "r"(a[3]), "r"(b0), "r"(b1));
}

// ---------------------------------------------------------------------------
__global__ void __launch_bounds__(NT, 1)
noteaxis_lstm(const float* __restrict__ nf, const float* __restrict__ tg,
              float* __restrict__ out)
{
    extern __shared__ __align__(16) char smem[];
    const uint32_t sb = (uint32_t)__cvta_generic_to_shared(smem);
    const int tid = threadIdx.x, warp = tid >> 5, lane = tid & 31;
    const int mh = warp & 1, nq = warp >> 1;      // rows mh*16.., cols nq*64..
    const int b0 = blockIdx.x * BT;
    const int lr = lane >> 2, lc = lane & 3;

    // zero A blocks (h starts at 0); stage bias/wout/bout
    for (int i = tid; i < 6 * ABLK / 4; i += NT)
        reinterpret_cast<uint32_t*>(smem)[i] = 0u;
    for (int i = tid; i < 1024; i += NT)
        reinterpret_cast<float*>(smem + SM_BIAS)[i] = g_biasn[i];
    if (tid < 128) reinterpret_cast<float*>(smem + SM_WOUT)[tid] = g_wout[tid];
    if (tid == 0)  reinterpret_cast<float*>(smem + SM_BOUT)[0] = g_bout[0];

    const int rowg = mh * 16 + lr + 8 * (lane & 1);      // this thread's C row
    float cs0[8], cs1[8];
#pragma unroll
    for (int i = 0; i < 8; ++i) { cs0[i] = 0.f; cs1[i] = 0.f; }

    const uint32_t aoff = (uint32_t)((mh * 16 + lr) * ASTR + lc * 4);
    const uint32_t boff = (uint32_t)(nq * 8 * 256 + lane * 8);   // 8 ntiles/warp

    // prologue: prefetch groups 0,1
    prefetch_group(sb + SM_RING, reinterpret_cast<const char*>(g_Bf), tid);
    prefetch_group(sb + SM_RING + GROUP, reinterpret_cast<const char*>(g_Bf) + GROUP, tid);
    int pseq = 2, gbuf = 0;
    __syncthreads();

    float* part = reinterpret_cast<float*>(smem + SM_PART);

    for (int t = 0; t < NSTEP; ++t) {
        // ---- stage x_t split hi/lo into blocks 0,1 -------------------------
#pragma unroll
        for (int i = 0; i < 8; ++i) {
            int idx = tid + i * NT;          // 0..4095
            int row = idx >> 7, f = idx & 127;
            float v;
            if (f < FDIM) v = nf[((size_t)(b0 + row) * NSTEP + t) * FDIM + f];
            else          v = t ? tg[(size_t)(b0 + row) * NSTEP + t - 1] : 0.f;
            __nv_bfloat16 hi = __float2bfloat16_rn(v);
            __nv_bfloat16 lo = __float2bfloat16_rn(v - __bfloat162float(hi));
            int eo = row * (ASTR / 2) + f;
            reinterpret_cast<__nv_bfloat16*>(smem)[eo] = hi;
            reinterpret_cast<__nv_bfloat16*>(smem + ABLK)[eo] = lo;
        }
        // first group-barrier below orders staging before GEMM reads

#pragma unroll 1
        for (int L = 0; L < 2; ++L) {
            float acc[32];
#pragma unroll
            for (int i = 0; i < 32; ++i) acc[i] = 0.f;

#pragma unroll 1
            for (int gi = 0; gi < 16; ++gi) {
                asm volatile("cp.async.wait_group 1;" ::: "memory");
                __syncthreads();
                int tbuf = gbuf + 2; if (tbuf >= 3) tbuf -= 3;
                prefetch_group(sb + SM_RING + (uint32_t)tbuf * GROUP,
                               reinterpret_cast<const char*>(g_Bf) + (size_t)pseq * GROUP, tid);
                pseq = (pseq + 1) & 31;

#pragma unroll
                for (int sp = 0; sp < 2; ++sp) {
                    const int p = 2 * gi + sp;          // piece within layer seq
                    const int T = p >> 4, kc = p & 15;
                    const int hiblk = (L == 0) ? (kc < 8 ? 0 : 2) : (kc < 8 ? 2 : 4);
                    const uint32_t kb = (uint32_t)((kc & 7) * 32);
                    uint32_t aH[4], aL[4];
                    ldA(sb + (uint32_t)hiblk * ABLK + aoff + kb, aH);
                    if (T == 0) ldA(sb + (uint32_t)(hiblk + 1) * ABLK + aoff + kb, aL);

                    uint32_t bb = sb + SM_RING + (uint32_t)gbuf * GROUP
                                + (uint32_t)sp * PIECE + boff;
#pragma unroll
                    for (int nt = 0; nt < 8; ++nt) {
                        uint32_t w0, w1;
                        asm volatile("ld.shared.v2.u32 {%0, %1}, [%2];"
                                     : "=r"(w0), "=r"(w1) : "r"(bb + (uint32_t)nt * 256));
                        mma16816(acc + nt * 4, aH, w0, w1);
                        if (T == 0) mma16816(acc + nt * 4, aL, w0, w1);
                    }
                }
                if (++gbuf == 3) gbuf = 0;
            }
            __syncthreads();   // all GEMM reads done before epilogue h writes

            // ---------------- epilogue: gates -> cells -> h ----------------
            const float* bias = reinterpret_cast<const float*>(smem + SM_BIAS) + L * 512;
            const float* wo = reinterpret_cast<const float*>(smem + SM_WOUT);
            float* cs = L ? cs1 : cs0;
            __nv_bfloat16* Hhi = reinterpret_cast<__nv_bfloat16*>(smem + (size_t)(2 + 2 * L) * ABLK);
            __nv_bfloat16* Hlo = reinterpret_cast<__nv_bfloat16*>(smem + (size_t)(3 + 2 * L) * ABLK);
            float dot = 0.f;
#pragma unroll
            for (int nt = 0; nt < 8; ++nt) {
                float c0 = acc[nt * 4], c1 = acc[nt * 4 + 1];
                float c2 = acc[nt * 4 + 2], c3 = acc[nt * 4 + 3];
                int n0 = nq * 64 + nt * 8 + 2 * lc;
                float2 bb2 = *reinterpret_cast<const float2*>(bias + n0);
                c0 += bb2.x; c1 += bb2.y; c2 += bb2.x; c3 += bb2.y;
                bool odd = (lane & 1);
                float v1 = __shfl_xor_sync(0xffffffffu, odd ? c0 : c2, 1);
                float v2 = __shfl_xor_sync(0xffffffffu, odd ? c1 : c3, 1);
                float gi_ = odd ? v1 : c0;
                float gf  = odd ? v2 : c1;
                float gg  = odd ? c2 : v1;
                float go  = odd ? c3 : v2;
                float c = fsig(gf) * cs[nt] + fsig(gi_) * ftanh_(gg);
                cs[nt] = c;
                float h = fsig(go) * ftanh_(c);
                int u = nq * 16 + nt * 2 + (lc >> 1);
                __nv_bfloat16 hh = __float2bfloat16_rn(h);
                __nv_bfloat16 hl = __float2bfloat16_rn(h - __bfloat162float(hh));
                int eo = rowg * (ASTR / 2) + u;
                Hhi[eo] = hh;
                Hlo[eo] = hl;
                if (L) dot = fmaf(h, wo[u], dot);
            }
            if (L) {
                dot += __shfl_xor_sync(0xffffffffu, dot, 2);
                if ((lane & 2) == 0) part[nq * 32 + rowg] = dot;
            }
            // next loop's first group-barrier orders h writes before reads
        }

        __syncthreads();   // h1 + partials visible
        if (tid < 32) {
            float s = reinterpret_cast<const float*>(smem + SM_BOUT)[0];
#pragma unroll
            for (int j = 0; j < 8; ++j) s += part[j * 32 + tid];
            out[(size_t)(b0 + tid) * NSTEP + t] = fsig(s);
        }
        // next-step x staging writes blocks 0,1 only; the first group-barrier
        // of the next step orders it against all readers.
    }
}

// ---------------------------------------------------------------------------
extern "C" void kernel_launch(void* const* d_in, const int* in_sizes, int n_in,
                              void* d_out, int out_size)
{
    const float* nf   = (const float*)d_in[0];
    const float* tg   = (const float*)d_in[1];
    const float* wih0 = (const float*)d_in[2];
    const float* whh0 = (const float*)d_in[3];
    const float* bih0 = (const float*)d_in[4];
    const float* bhh0 = (const float*)d_in[5];
    const float* wih1 = (const float*)d_in[6];
    const float* whh1 = (const float*)d_in[7];
    const float* bih1 = (const float*)d_in[8];
    const float* bhh1 = (const float*)d_in[9];
    const float* wout = (const float*)d_in[10];
    const float* bout = (const float*)d_in[11];
    float* out = (float*)d_out;

    cudaFuncSetAttribute(noteaxis_lstm, cudaFuncAttributeMaxDynamicSharedMemorySize, SMEM_SZ);

    noteaxis_prep<<<(64 * 2048 + 255) / 256, 256>>>(wih0, whh0, bih0, bhh0,
                                                    wih1, whh1, bih1, bhh1,
                                                    wout, bout);
    noteaxis_lstm<<<NCTA, NT, SMEM_SZ>>>(nf, tg, out);
}